// round 11
// baseline (speedup 1.0000x reference)
#include <cuda_runtime.h>

// EM-routing capsule layer. B=64, S=14, I=32 -> N=6272/batch, C=10, D=16, 3 iters.
// Pass 0 linearized. R11: barrier-free routing passes (lane = (spatial j, class c),
// warp pinned to capsule i; softmax via intra-warp shfl; pose direct from GMEM).
// Fix vs R10: epilogue g_partial write grid-strided (tid<330 with 256 threads
// left classes 8,9 unwritten -> NaN).

#define BB   64
#define SSQ  196
#define II   32
#define CCL  10
#define EPSf 1e-9f
#define L2E  1.4426950408889634f

typedef unsigned long long u64;

__device__ float g0[128 * 10 * 69 * 32];        // pass0 per-(cta,warp) slabs
__device__ float g_partial[512 * CCL * 34];     // per accum-CTA: [0]=rsum [1..16]=sv [17..32]=sv2
__device__ float g_stats[BB * CCL * 34];        // per (b,c): [0..15]=nms [16..31]=siv [32]=cst (log2)

__device__ __forceinline__ u64 pack2(float lo, float hi) {
    u64 r; asm("mov.b64 %0,{%1,%2};" : "=l"(r) : "f"(lo), "f"(hi)); return r;
}
__device__ __forceinline__ void unpack2(u64 v, float& lo, float& hi) {
    asm("mov.b64 {%0,%1},%2;" : "=f"(lo), "=f"(hi) : "l"(v));
}
__device__ __forceinline__ u64 fma2(u64 a, u64 b, u64 c) {
    u64 d; asm("fma.rn.f32x2 %0,%1,%2,%3;" : "=l"(d) : "l"(a), "l"(b), "l"(c)); return d;
}
__device__ __forceinline__ u64 add2(u64 a, u64 b) {
    u64 d; asm("add.rn.f32x2 %0,%1,%2;" : "=l"(d) : "l"(a), "l"(b)); return d;
}
__device__ __forceinline__ u64 mul2(u64 a, u64 b) {
    u64 d; asm("mul.rn.f32x2 %0,%1,%2;" : "=l"(d) : "l"(a), "l"(b)); return d;
}
__device__ __forceinline__ float ex2f(float x) {
    float y; asm("ex2.approx.f32 %0,%1;" : "=f"(y) : "f"(x)); return y;
}

// ---------------- pass 0: linear/quadratic reduction over pose ----------------
__global__ __launch_bounds__(320, 1)
void pass0_kernel(const float* __restrict__ pose, const float* __restrict__ act)
{
    const int cta = blockIdx.x, b = cta >> 1, half = cta & 1;
    const int wpid = threadIdx.x >> 5, i = threadIdx.x & 31;

    float aP[16], G[40], X1[4], X2[4];
    float ra = 0.f, rc1 = 0.f, rc2 = 0.f, rq1 = 0.f, rq2 = 0.f;
    #pragma unroll
    for (int f = 0; f < 16; f++) aP[f] = 0.f;
    #pragma unroll
    for (int f = 0; f < 40; f++) G[f] = 0.f;
    #pragma unroll
    for (int f = 0; f < 4; f++) { X1[f] = 0.f; X2[f] = 0.f; }

    for (int sl = wpid; sl < 98; sl += 10) {
        const int s  = half * 98 + sl;
        const int h  = s / 14;
        const int wx = s - h * 14;
        const float cr = (h  + 0.5f) * (1.0f / 14.0f);
        const float cw = (wx + 0.5f) * (1.0f / 14.0f);

        const size_t nidx = ((size_t)(b * SSQ + s) * II + i);
        const float4* pv = reinterpret_cast<const float4*>(pose + nidx * 16);
        float p16[16];
        #pragma unroll
        for (int q4 = 0; q4 < 4; q4++) {
            float4 t = pv[q4];
            p16[q4*4+0] = t.x; p16[q4*4+1] = t.y; p16[q4*4+2] = t.z; p16[q4*4+3] = t.w;
        }
        const float a = act[nidx];

        #pragma unroll
        for (int p = 0; p < 4; p++) {
            float t0 = a * p16[p*4+0], t1 = a * p16[p*4+1];
            float t2 = a * p16[p*4+2], t3 = a * p16[p*4+3];
            aP[p*4+0] += t0; aP[p*4+1] += t1; aP[p*4+2] += t2; aP[p*4+3] += t3;
            float* Gp = G + p * 10;
            Gp[0] = fmaf(t0, p16[p*4+0], Gp[0]);
            Gp[1] = fmaf(t0, p16[p*4+1], Gp[1]);
            Gp[2] = fmaf(t0, p16[p*4+2], Gp[2]);
            Gp[3] = fmaf(t0, p16[p*4+3], Gp[3]);
            Gp[4] = fmaf(t1, p16[p*4+1], Gp[4]);
            Gp[5] = fmaf(t1, p16[p*4+2], Gp[5]);
            Gp[6] = fmaf(t1, p16[p*4+3], Gp[6]);
            Gp[7] = fmaf(t2, p16[p*4+2], Gp[7]);
            Gp[8] = fmaf(t2, p16[p*4+3], Gp[8]);
            Gp[9] = fmaf(t3, p16[p*4+3], Gp[9]);
        }
        ra += a;
        const float acr = a * cr, acw = a * cw;
        rc1 += acr; rc2 += acw;
        rq1 = fmaf(acr, cr, rq1); rq2 = fmaf(acw, cw, rq2);
        #pragma unroll
        for (int q = 0; q < 4; q++) {
            X1[q] = fmaf(acr, p16[q], X1[q]);
            X2[q] = fmaf(acw, p16[q], X2[q]);
        }
    }

    float* o = g0 + (size_t)(cta * 10 + wpid) * 69 * 32 + i;
    #pragma unroll
    for (int f = 0; f < 16; f++) o[f * 32] = aP[f];
    #pragma unroll
    for (int f = 0; f < 40; f++) o[(16 + f) * 32] = G[f];
    o[56 * 32] = ra;
    o[57 * 32] = rc1; o[58 * 32] = rc2;
    o[59 * 32] = rq1; o[60 * 32] = rq2;
    #pragma unroll
    for (int f = 0; f < 4; f++) { o[(61 + f) * 32] = X1[f]; o[(65 + f) * 32] = X2[f]; }
}

// ---------------- pass 0 stats ----------------
__global__ __launch_bounds__(320, 1)
void stats0_kernel(const float* __restrict__ wt,
                   const float* __restrict__ beta_v,
                   const float* __restrict__ beta_a)
{
    __shared__ float sm[32][72];
    const int b = blockIdx.x, tid = threadIdx.x;

    for (int t = tid; t < 32 * 69; t += 320) {
        const int i = t / 69, f = t - i * 69;
        float s = 0.f;
        #pragma unroll
        for (int k = 0; k < 20; k++) {
            const int cta = b * 2 + (k >= 10 ? 1 : 0);
            const int ww  = k - (k >= 10 ? 10 : 0);
            s += g0[(size_t)(cta * 10 + ww) * 69 * 32 + f * 32 + i];
        }
        sm[i][f] = s;
    }
    __syncthreads();

    if (tid < 160) {
        const int c = tid >> 4, d = tid & 15, p = d >> 2, r = d & 3;
        float RA = 0.f, RC = 0.f, RQ = 0.f, Sv = 0.f, Sv2 = 0.f, Cr = 0.f;
        for (int i = 0; i < 32; i++) {
            const float* g = sm[i];
            const float* wr = wt + (i * CCL + c) * 16;
            const float W0 = wr[0*4+r], W1 = wr[1*4+r], W2 = wr[2*4+r], W3 = wr[3*4+r];
            const float* ap = g + p * 4;
            Sv += ap[0]*W0 + ap[1]*W1 + ap[2]*W2 + ap[3]*W3;
            const float* Gp = g + 16 + p * 10;
            Sv2 += W0*W0*Gp[0] + W1*W1*Gp[4] + W2*W2*Gp[7] + W3*W3*Gp[9]
                 + 2.f*(W0*W1*Gp[1] + W0*W2*Gp[2] + W0*W3*Gp[3]
                      + W1*W2*Gp[5] + W1*W3*Gp[6] + W2*W3*Gp[8]);
            RA += g[56];
            if (d == 0) { RC += g[57]; RQ += g[59]; Cr += W0*g[61]+W1*g[62]+W2*g[63]+W3*g[64]; }
            else if (d == 1) { RC += g[58]; RQ += g[60]; Cr += W0*g[65]+W1*g[66]+W2*g[67]+W3*g[68]; }
        }
        float coordm = (d == 0 || d == 1) ? RC : 0.f;
        float coordv = (d == 0 || d == 1) ? (2.f * Cr + RQ) : 0.f;
        float mean = (Sv + coordm) / RA;
        float var  = fmaxf((Sv2 + coordv) / RA - mean * mean, 0.f);
        float lg   = __logf(sqrtf(var) + EPSf);
        float rr_sum = RA * 0.1f;
        float cost = (beta_v[c] + lg) * rr_sum, lgs = lg;
        #pragma unroll
        for (int off = 8; off; off >>= 1) {
            cost += __shfl_xor_sync(0xffffffffu, cost, off, 16);
            lgs  += __shfl_xor_sync(0xffffffffu, lgs,  off, 16);
        }
        float oact = 1.f / (1.f + __expf(-(beta_a[c] - cost)));   // invT = 1
        float siv  = sqrtf(L2E / (2.f * var + EPSf));
        float* st = g_stats + (b * CCL + c) * 34;
        st[d]      = -mean * siv;
        st[16 + d] = siv;
        if (d == 0) st[32] = (__logf(oact + EPSf) - lgs) * L2E;
    }
}

// ---------------- routing passes 1 and 2: barrier-free ----------------
// CTA = 256 threads = 8 warps. Warp w pinned to capsule i = octet*8 + w.
// Lane = (j = lane/10 spatial slot, c = lane%10 class); lanes 30,31 idle (a=0).
// Step t covers s_loc = 3t + j. No __syncthreads in mainloop.
template<int IT>
__global__ __launch_bounds__(256, 2)
void accum_kernel(const float* __restrict__ pose,
                  const float* __restrict__ act,
                  const float* __restrict__ wt,
                  const float* __restrict__ beta_v,
                  const float* __restrict__ beta_a)
{
    __shared__ __align__(16) float s_stat[CCL][8][4];  // per pair: nms0,nms1,siv0,siv1
    __shared__ float  s_cst[CCL];
    __shared__ float2 s_coord[98];
    __shared__ float  s_slab[8][CCL][33];              // epilogue cross-warp reduce

    const int cta = blockIdx.x;
    const int b = cta >> 3, octet = (cta >> 1) & 3, half = cta & 1;
    const int tid = threadIdx.x, w = tid >> 5, lane = tid & 31;
    const int i = octet * 8 + w;

    // ---- stats into smem ----
    if (tid < 160) {
        const int cc = tid >> 4, d = tid & 15;
        float nmsv, sivv, cstv = 0.f;
        if (IT == 1) {
            const float* st = g_stats + (b * CCL + cc) * 34;
            nmsv = st[d]; sivv = st[16 + d];
            if (d == 0) cstv = st[32];
        } else {
            float rsum0 = 0.f, sva = 0.f, sv2a = 0.f;
            #pragma unroll
            for (int q = 0; q < 8; q++) {
                const float* p = g_partial + ((b * 8 + q) * CCL + cc) * 34;
                rsum0 += p[0]; sva += p[1 + d]; sv2a += p[17 + d];
            }
            float mean = sva / rsum0;
            float var  = fmaxf(sv2a / rsum0 - mean * mean, 0.f);
            float lg   = __logf(sqrtf(var) + EPSf);
            float cost = (beta_v[cc] + lg) * rsum0, lgs = lg;
            #pragma unroll
            for (int off = 8; off; off >>= 1) {
                cost += __shfl_xor_sync(0xffffffffu, cost, off, 16);
                lgs  += __shfl_xor_sync(0xffffffffu, lgs,  off, 16);
            }
            float oact = 1.f / (1.f + __expf(-2.0f * (beta_a[cc] - cost)));  // invT = 2
            sivv = sqrtf(L2E / (2.f * var + EPSf));
            nmsv = -mean * sivv;
            if (d == 0) cstv = (__logf(oact + EPSf) - lgs) * L2E;
        }
        s_stat[cc][d >> 1][d & 1]       = nmsv;
        s_stat[cc][d >> 1][2 + (d & 1)] = sivv;
        if (d == 0) s_cst[cc] = cstv;
    } else {
        for (int x = tid - 160; x < 98; x += 96) {
            const int s = half * 98 + x;
            const int h = s / 14, wx = s - h * 14;
            s_coord[x] = make_float2((h + 0.5f) * (1.0f/14.0f), (wx + 0.5f) * (1.0f/14.0f));
        }
    }
    __syncthreads();   // the ONLY pre-mainloop barrier

    // lane decode (lanes 30,31 clamp into group 2, contributions zeroed via a=0)
    int j = lane / 10; if (j > 2) j = 2;
    const bool lane_ok = (lane < 30);
    int c = lane - j * 10; if (c > 9) c = 9;

    // W in registers (warp's i fixed)
    u64 W2[4][2];
    {
        const float* wr = wt + (i * CCL + c) * 16;
        #pragma unroll
        for (int q = 0; q < 4; q++) {
            W2[q][0] = pack2(wr[q*4+0], wr[q*4+1]);
            W2[q][1] = pack2(wr[q*4+2], wr[q*4+3]);
        }
    }
    const float cstc = s_cst[c];
    const unsigned stat_base = (unsigned)__cvta_generic_to_shared(&s_stat[c][0][0]);

    // softmax gather lane indices (within this lane's 10-class group)
    int gidx[9];
    #pragma unroll
    for (int k = 1; k <= 9; k++) {
        int cc = c + k; if (cc >= 10) cc -= 10;
        gidx[k - 1] = j * 10 + cc;
    }

    u64 sv[8], sv2[8];
    #pragma unroll
    for (int jj = 0; jj < 8; jj++) { sv[jj] = 0ULL; sv2[jj] = 0ULL; }
    float rsum = 0.f;

    const float4* pose4 = reinterpret_cast<const float4*>(pose);
    const size_t rbase = ((size_t)(b * SSQ) + half * 98) * II + i;

    // preload step 0 (s_loc = j)
    float4 P0, P1, P2, P3; float a;
    {
        const size_t row = rbase + (size_t)j * II;
        const float4* pp = pose4 + row * 4;
        P0 = pp[0]; P1 = pp[1]; P2 = pp[2]; P3 = pp[3];
        a = lane_ok ? act[row] : 0.f;
    }

    for (int t = 0; t < 33; t++) {
        // prefetch step t+1
        float4 F0, F1, F2, F3; float an;
        if (t < 32) {
            int sln = 3 * (t + 1) + j;
            const bool vn = lane_ok && (sln < 98);
            if (sln > 97) sln = 97;
            const size_t row = rbase + (size_t)sln * II;
            const float4* pp = pose4 + row * 4;
            F0 = pp[0]; F1 = pp[1]; F2 = pp[2]; F3 = pp[3];
            an = vn ? act[row] : 0.f;
        }

        int sl = 3 * t + j;
        if (sl > 97) sl = 97;                 // clamp (a already zeroed for invalid)
        const float2 cc2 = s_coord[sl];

        // votes (r-paired f32x2), coords folded into pair (d0,d1)
        u64 v2[8];
        v2[0] = pack2(cc2.x, cc2.y);
        #pragma unroll
        for (int jj = 1; jj < 8; jj++) v2[jj] = 0ULL;
        {
            u64 pp;
            pp = pack2(P0.x, P0.x); v2[0] = fma2(pp, W2[0][0], v2[0]); v2[1] = fma2(pp, W2[0][1], v2[1]);
            pp = pack2(P0.y, P0.y); v2[0] = fma2(pp, W2[1][0], v2[0]); v2[1] = fma2(pp, W2[1][1], v2[1]);
            pp = pack2(P0.z, P0.z); v2[0] = fma2(pp, W2[2][0], v2[0]); v2[1] = fma2(pp, W2[2][1], v2[1]);
            pp = pack2(P0.w, P0.w); v2[0] = fma2(pp, W2[3][0], v2[0]); v2[1] = fma2(pp, W2[3][1], v2[1]);
            pp = pack2(P1.x, P1.x); v2[2] = fma2(pp, W2[0][0], v2[2]); v2[3] = fma2(pp, W2[0][1], v2[3]);
            pp = pack2(P1.y, P1.y); v2[2] = fma2(pp, W2[1][0], v2[2]); v2[3] = fma2(pp, W2[1][1], v2[3]);
            pp = pack2(P1.z, P1.z); v2[2] = fma2(pp, W2[2][0], v2[2]); v2[3] = fma2(pp, W2[2][1], v2[3]);
            pp = pack2(P1.w, P1.w); v2[2] = fma2(pp, W2[3][0], v2[2]); v2[3] = fma2(pp, W2[3][1], v2[3]);
            pp = pack2(P2.x, P2.x); v2[4] = fma2(pp, W2[0][0], v2[4]); v2[5] = fma2(pp, W2[0][1], v2[5]);
            pp = pack2(P2.y, P2.y); v2[4] = fma2(pp, W2[1][0], v2[4]); v2[5] = fma2(pp, W2[1][1], v2[5]);
            pp = pack2(P2.z, P2.z); v2[4] = fma2(pp, W2[2][0], v2[4]); v2[5] = fma2(pp, W2[2][1], v2[5]);
            pp = pack2(P2.w, P2.w); v2[4] = fma2(pp, W2[3][0], v2[4]); v2[5] = fma2(pp, W2[3][1], v2[5]);
            pp = pack2(P3.x, P3.x); v2[6] = fma2(pp, W2[0][0], v2[6]); v2[7] = fma2(pp, W2[0][1], v2[7]);
            pp = pack2(P3.y, P3.y); v2[6] = fma2(pp, W2[1][0], v2[6]); v2[7] = fma2(pp, W2[1][1], v2[7]);
            pp = pack2(P3.z, P3.z); v2[6] = fma2(pp, W2[2][0], v2[6]); v2[7] = fma2(pp, W2[2][1], v2[7]);
            pp = pack2(P3.w, P3.w); v2[6] = fma2(pp, W2[3][0], v2[6]); v2[7] = fma2(pp, W2[3][1], v2[7]);
        }

        // zz (log2 domain): cst - sum ((v-m)*siv)^2
        u64 az0 = 0ULL, az1 = 0ULL;
        #pragma unroll
        for (int jj = 0; jj < 8; jj++) {
            u64 nm, sviv;
            asm volatile("ld.shared.v2.b64 {%0,%1},[%2];"
                         : "=l"(nm), "=l"(sviv) : "r"(stat_base + 16u * jj));
            u64 tt = fma2(v2[jj], sviv, nm);
            if (jj & 1) az1 = fma2(tt, tt, az1);
            else        az0 = fma2(tt, tt, az0);
        }
        float l0, h0, l1, h1;
        unpack2(az0, l0, h0); unpack2(az1, l1, h1);
        const float zz = cstc - ((l0 + l1) + (h0 + h1));

        // self-shifted softmax via intra-warp shuffles (NO barrier, NO smem)
        float Z = 1.0f;   // self term exp2(0)
        #pragma unroll
        for (int k = 0; k < 9; k++) {
            const float zo = __shfl_sync(0xffffffffu, zz, gidx[k]);
            Z += ex2f(zo - zz);
        }
        const float rr = __fdividef(a, Z);   // a pre-zeroed for invalid lanes/steps

        rsum += rr;
        const u64 rr2 = pack2(rr, rr);
        #pragma unroll
        for (int jj = 0; jj < 8; jj++) {
            const u64 rv = mul2(rr2, v2[jj]);
            sv[jj]  = add2(sv[jj], rv);
            sv2[jj] = fma2(rv, v2[jj], sv2[jj]);
        }

        if (t < 32) { P0 = F0; P1 = F1; P2 = F2; P3 = F3; a = an; }
    }

    // ---- epilogue: reduce j-groups within warp (lanes c, c+10, c+20 -> lane c) ----
    rsum += __shfl_sync(0xffffffffu, rsum, lane + 10) + __shfl_sync(0xffffffffu, rsum, lane + 20);
    #pragma unroll
    for (int jj = 0; jj < 8; jj++) {
        sv[jj]  = add2(sv[jj],  add2(__shfl_sync(0xffffffffu, sv[jj],  lane + 10),
                                     __shfl_sync(0xffffffffu, sv[jj],  lane + 20)));
        sv2[jj] = add2(sv2[jj], add2(__shfl_sync(0xffffffffu, sv2[jj], lane + 10),
                                     __shfl_sync(0xffffffffu, sv2[jj], lane + 20)));
    }
    if (lane < 10) {
        float* o = &s_slab[w][lane][0];
        o[0] = rsum;
        #pragma unroll
        for (int jj = 0; jj < 8; jj++) {
            float lo, hi;
            unpack2(sv[jj],  lo, hi); o[1  + 2*jj] = lo; o[2  + 2*jj] = hi;
            unpack2(sv2[jj], lo, hi); o[17 + 2*jj] = lo; o[18 + 2*jj] = hi;
        }
    }
    __syncthreads();

    // cross-warp (over 8 capsules) sum -> g_partial  [FIX: grid-stride over 330]
    for (int t = tid; t < CCL * 33; t += 256) {
        const int cc = t / 33, f = t - cc * 33;
        float s = 0.f;
        #pragma unroll
        for (int ww = 0; ww < 8; ww++) s += s_slab[ww][cc][f];
        g_partial[(cta * CCL + cc) * 34 + f] = s;
    }
}

// ---------------- final output ----------------
__global__ __launch_bounds__(160)
void finalize_out(const float* __restrict__ beta_v,
                  const float* __restrict__ beta_a,
                  float* __restrict__ out)
{
    const int b = blockIdx.x;
    const int c = threadIdx.x >> 4;
    const int d = threadIdx.x & 15;

    float rsum = 0.f, sv = 0.f, sv2 = 0.f;
    #pragma unroll
    for (int q = 0; q < 8; q++) {
        const float* p = g_partial + ((b * 8 + q) * CCL + c) * 34;
        rsum += p[0]; sv += p[1 + d]; sv2 += p[17 + d];
    }
    float mean = sv / rsum;
    float var  = fmaxf(sv2 / rsum - mean * mean, 0.f);
    float lg   = __logf(sqrtf(var) + EPSf);
    float cost = (beta_v[c] + lg) * rsum;
    #pragma unroll
    for (int off = 8; off; off >>= 1)
        cost += __shfl_xor_sync(0xffffffffu, cost, off, 16);

    float oact = 1.f / (1.f + __expf(-3.0f * (beta_a[c] - cost)));   // invT = 3

    out[(b * CCL + c) * 16 + d] = mean;
    if (d == 0) out[BB * CCL * 16 + b * CCL + c] = oact;
}

extern "C" void kernel_launch(void* const* d_in, const int* in_sizes, int n_in,
                              void* d_out, int out_size)
{
    const float* pose = (const float*)d_in[0];
    const float* act  = (const float*)d_in[1];
    const float* w    = (const float*)d_in[2];
    const float* bv   = (const float*)d_in[3];
    const float* ba   = (const float*)d_in[4];
    float* out = (float*)d_out;

    pass0_kernel <<<128, 320>>>(pose, act);
    stats0_kernel<<<64, 320>>>(w, bv, ba);
    accum_kernel<1><<<512, 256>>>(pose, act, w, bv, ba);
    accum_kernel<2><<<512, 256>>>(pose, act, w, bv, ba);
    finalize_out <<<64, 160>>>(bv, ba, out);
}

// round 13
// speedup vs baseline: 1.8045x; 1.8045x over previous
#include <cuda_runtime.h>

// EM-routing capsule layer. B=64, S=14, I=32 -> N=6272/batch, C=10, D=16, 3 iters.
// Pass 0 linearized. R13 == R12 + __align__(16) on s_stat (ld.shared.v2.b64
// requires 16B alignment; flat float array was only 4B-aligned -> trap).
// Routing passes: lane=(i-group j, class c), warp w owns i in {w,w+10,w+20},
// softmax via intra-warp shfl, smem ring-4 duplicated-pose tiles.

#define BB   64
#define SSQ  196
#define II   32
#define CCL  10
#define EPSf 1e-9f
#define L2E  1.4426950408889634f

typedef unsigned long long u64;

__device__ float g0[128 * 10 * 69 * 32];        // pass0 per-(cta,warp) slabs
__device__ float g_partial[256 * CCL * 34];     // per (b*4+sl, c): [0]=rsum [1..16]=sv [17..32]=sv2
__device__ float g_stats[BB * CCL * 34];        // per (b,c): [0..15]=nms [16..31]=siv [32]=cst (log2)

__device__ __forceinline__ u64 pack2(float lo, float hi) {
    u64 r; asm("mov.b64 %0,{%1,%2};" : "=l"(r) : "f"(lo), "f"(hi)); return r;
}
__device__ __forceinline__ void unpack2(u64 v, float& lo, float& hi) {
    asm("mov.b64 {%0,%1},%2;" : "=f"(lo), "=f"(hi) : "l"(v));
}
__device__ __forceinline__ u64 fma2(u64 a, u64 b, u64 c) {
    u64 d; asm("fma.rn.f32x2 %0,%1,%2,%3;" : "=l"(d) : "l"(a), "l"(b), "l"(c)); return d;
}
__device__ __forceinline__ u64 add2(u64 a, u64 b) {
    u64 d; asm("add.rn.f32x2 %0,%1,%2;" : "=l"(d) : "l"(a), "l"(b)); return d;
}
__device__ __forceinline__ u64 mul2(u64 a, u64 b) {
    u64 d; asm("mul.rn.f32x2 %0,%1,%2;" : "=l"(d) : "l"(a), "l"(b)); return d;
}
__device__ __forceinline__ float ex2f(float x) {
    float y; asm("ex2.approx.f32 %0,%1;" : "=f"(y) : "f"(x)); return y;
}

// ---------------- pass 0: linear/quadratic reduction over pose ----------------
__global__ __launch_bounds__(320, 1)
void pass0_kernel(const float* __restrict__ pose, const float* __restrict__ act)
{
    const int cta = blockIdx.x, b = cta >> 1, half = cta & 1;
    const int wpid = threadIdx.x >> 5, i = threadIdx.x & 31;

    float aP[16], G[40], X1[4], X2[4];
    float ra = 0.f, rc1 = 0.f, rc2 = 0.f, rq1 = 0.f, rq2 = 0.f;
    #pragma unroll
    for (int f = 0; f < 16; f++) aP[f] = 0.f;
    #pragma unroll
    for (int f = 0; f < 40; f++) G[f] = 0.f;
    #pragma unroll
    for (int f = 0; f < 4; f++) { X1[f] = 0.f; X2[f] = 0.f; }

    for (int sl = wpid; sl < 98; sl += 10) {
        const int s  = half * 98 + sl;
        const int h  = s / 14;
        const int wx = s - h * 14;
        const float cr = (h  + 0.5f) * (1.0f / 14.0f);
        const float cw = (wx + 0.5f) * (1.0f / 14.0f);

        const size_t nidx = ((size_t)(b * SSQ + s) * II + i);
        const float4* pv = reinterpret_cast<const float4*>(pose + nidx * 16);
        float p16[16];
        #pragma unroll
        for (int q4 = 0; q4 < 4; q4++) {
            float4 t = pv[q4];
            p16[q4*4+0] = t.x; p16[q4*4+1] = t.y; p16[q4*4+2] = t.z; p16[q4*4+3] = t.w;
        }
        const float a = act[nidx];

        #pragma unroll
        for (int p = 0; p < 4; p++) {
            float t0 = a * p16[p*4+0], t1 = a * p16[p*4+1];
            float t2 = a * p16[p*4+2], t3 = a * p16[p*4+3];
            aP[p*4+0] += t0; aP[p*4+1] += t1; aP[p*4+2] += t2; aP[p*4+3] += t3;
            float* Gp = G + p * 10;
            Gp[0] = fmaf(t0, p16[p*4+0], Gp[0]);
            Gp[1] = fmaf(t0, p16[p*4+1], Gp[1]);
            Gp[2] = fmaf(t0, p16[p*4+2], Gp[2]);
            Gp[3] = fmaf(t0, p16[p*4+3], Gp[3]);
            Gp[4] = fmaf(t1, p16[p*4+1], Gp[4]);
            Gp[5] = fmaf(t1, p16[p*4+2], Gp[5]);
            Gp[6] = fmaf(t1, p16[p*4+3], Gp[6]);
            Gp[7] = fmaf(t2, p16[p*4+2], Gp[7]);
            Gp[8] = fmaf(t2, p16[p*4+3], Gp[8]);
            Gp[9] = fmaf(t3, p16[p*4+3], Gp[9]);
        }
        ra += a;
        const float acr = a * cr, acw = a * cw;
        rc1 += acr; rc2 += acw;
        rq1 = fmaf(acr, cr, rq1); rq2 = fmaf(acw, cw, rq2);
        #pragma unroll
        for (int q = 0; q < 4; q++) {
            X1[q] = fmaf(acr, p16[q], X1[q]);
            X2[q] = fmaf(acw, p16[q], X2[q]);
        }
    }

    float* o = g0 + (size_t)(cta * 10 + wpid) * 69 * 32 + i;
    #pragma unroll
    for (int f = 0; f < 16; f++) o[f * 32] = aP[f];
    #pragma unroll
    for (int f = 0; f < 40; f++) o[(16 + f) * 32] = G[f];
    o[56 * 32] = ra;
    o[57 * 32] = rc1; o[58 * 32] = rc2;
    o[59 * 32] = rq1; o[60 * 32] = rq2;
    #pragma unroll
    for (int f = 0; f < 4; f++) { o[(61 + f) * 32] = X1[f]; o[(65 + f) * 32] = X2[f]; }
}

// ---------------- pass 0 stats ----------------
__global__ __launch_bounds__(320, 1)
void stats0_kernel(const float* __restrict__ wt,
                   const float* __restrict__ beta_v,
                   const float* __restrict__ beta_a)
{
    __shared__ float sm[32][72];
    const int b = blockIdx.x, tid = threadIdx.x;

    for (int t = tid; t < 32 * 69; t += 320) {
        const int i = t / 69, f = t - i * 69;
        float s = 0.f;
        #pragma unroll
        for (int k = 0; k < 20; k++) {
            const int cta = b * 2 + (k >= 10 ? 1 : 0);
            const int ww  = k - (k >= 10 ? 10 : 0);
            s += g0[(size_t)(cta * 10 + ww) * 69 * 32 + f * 32 + i];
        }
        sm[i][f] = s;
    }
    __syncthreads();

    if (tid < 160) {
        const int c = tid >> 4, d = tid & 15, p = d >> 2, r = d & 3;
        float RA = 0.f, RC = 0.f, RQ = 0.f, Sv = 0.f, Sv2 = 0.f, Cr = 0.f;
        for (int i = 0; i < 32; i++) {
            const float* g = sm[i];
            const float* wr = wt + (i * CCL + c) * 16;
            const float W0 = wr[0*4+r], W1 = wr[1*4+r], W2 = wr[2*4+r], W3 = wr[3*4+r];
            const float* ap = g + p * 4;
            Sv += ap[0]*W0 + ap[1]*W1 + ap[2]*W2 + ap[3]*W3;
            const float* Gp = g + 16 + p * 10;
            Sv2 += W0*W0*Gp[0] + W1*W1*Gp[4] + W2*W2*Gp[7] + W3*W3*Gp[9]
                 + 2.f*(W0*W1*Gp[1] + W0*W2*Gp[2] + W0*W3*Gp[3]
                      + W1*W2*Gp[5] + W1*W3*Gp[6] + W2*W3*Gp[8]);
            RA += g[56];
            if (d == 0) { RC += g[57]; RQ += g[59]; Cr += W0*g[61]+W1*g[62]+W2*g[63]+W3*g[64]; }
            else if (d == 1) { RC += g[58]; RQ += g[60]; Cr += W0*g[65]+W1*g[66]+W2*g[67]+W3*g[68]; }
        }
        float coordm = (d == 0 || d == 1) ? RC : 0.f;
        float coordv = (d == 0 || d == 1) ? (2.f * Cr + RQ) : 0.f;
        float mean = (Sv + coordm) / RA;
        float var  = fmaxf((Sv2 + coordv) / RA - mean * mean, 0.f);
        float lg   = __logf(sqrtf(var) + EPSf);
        float rr_sum = RA * 0.1f;
        float cost = (beta_v[c] + lg) * rr_sum, lgs = lg;
        #pragma unroll
        for (int off = 8; off; off >>= 1) {
            cost += __shfl_xor_sync(0xffffffffu, cost, off, 16);
            lgs  += __shfl_xor_sync(0xffffffffu, lgs,  off, 16);
        }
        float oact = 1.f / (1.f + __expf(-(beta_a[c] - cost)));   // invT = 1
        float siv  = sqrtf(L2E / (2.f * var + EPSf));
        float* st = g_stats + (b * CCL + c) * 34;
        st[d]      = -mean * siv;
        st[16 + d] = siv;
        if (d == 0) st[32] = (__logf(oact + EPSf) - lgs) * L2E;
    }
}

// ---------------- routing passes 1 and 2 ----------------
// One unit = (pose row at smem addr base, swizzle key rk): votes -> zz -> shfl
// softmax -> accumulate. Entirely intra-warp.
struct Acc { u64 sv[8]; u64 sv2[8]; float rsum; };

__device__ __forceinline__ void process_unit(
    unsigned base, int rk, float2 cc2, float a,
    const u64 (&W2)[4][2], unsigned stat_base, float cstc, const int (&gidx)[9],
    Acc& acc)
{
    u64 v2[8];
    v2[0] = pack2(cc2.x, cc2.y);
    #pragma unroll
    for (int jj = 1; jj < 8; jj++) v2[jj] = 0ULL;

    #pragma unroll
    for (int g = 0; g < 8; g++) {
        u64 pa, pb;   // duplicated pose pairs (e,e) (e+1,e+1), e = 2g
        asm volatile("ld.shared.v2.b64 {%0,%1},[%2];"
                     : "=l"(pa), "=l"(pb) : "r"(base + (unsigned)((g ^ rk) << 4)));
        const int p = g >> 1, q0 = (g & 1) * 2;
        v2[p*2+0] = fma2(pa, W2[q0][0],   v2[p*2+0]);
        v2[p*2+1] = fma2(pa, W2[q0][1],   v2[p*2+1]);
        v2[p*2+0] = fma2(pb, W2[q0+1][0], v2[p*2+0]);
        v2[p*2+1] = fma2(pb, W2[q0+1][1], v2[p*2+1]);
    }

    u64 az0 = 0ULL, az1 = 0ULL;
    #pragma unroll
    for (int jj = 0; jj < 8; jj++) {
        u64 nm, sviv;
        asm volatile("ld.shared.v2.b64 {%0,%1},[%2];"
                     : "=l"(nm), "=l"(sviv) : "r"(stat_base + 16u * jj));
        u64 t = fma2(v2[jj], sviv, nm);
        if (jj & 1) az1 = fma2(t, t, az1);
        else        az0 = fma2(t, t, az0);
    }
    float l0, h0, l1, h1;
    unpack2(az0, l0, h0); unpack2(az1, l1, h1);
    const float zz = cstc - ((l0 + l1) + (h0 + h1));

    // self-shifted softmax via intra-warp shuffles
    float Z = 1.0f;
    #pragma unroll
    for (int k = 0; k < 9; k++)
        Z += ex2f(__shfl_sync(0xffffffffu, zz, gidx[k]) - zz);
    const float rr = __fdividef(a, Z);

    acc.rsum += rr;
    const u64 rr2 = pack2(rr, rr);
    #pragma unroll
    for (int jj = 0; jj < 8; jj++) {
        const u64 rv = mul2(rr2, v2[jj]);
        acc.sv[jj]  = add2(acc.sv[jj], rv);
        acc.sv2[jj] = fma2(rv, v2[jj], acc.sv2[jj]);
    }
}

template<int IT>
__global__ __launch_bounds__(320, 2)
void accum_kernel(const float* __restrict__ pose,
                  const float* __restrict__ act,
                  const float* __restrict__ wt,
                  const float* __restrict__ beta_v,
                  const float* __restrict__ beta_a)
{
    __shared__ float4 s_tile[4 * 256];     // ring-4: 32 rows x 8 granules, duplicated pose
    __shared__ float4 s_tailt[784];        // 98 rows (i=30,31 for all 49 s), duplicated
    __shared__ float  s_actr[4][32];
    __shared__ float  s_tact[98];
    __shared__ __align__(16) float s_stat[CCL * 68];  // 17 granules/class (bank-spread); 16B-aligned for v2.b64
    __shared__ float  s_cst[CCL];
    __shared__ float2 s_coord[49];
    __shared__ float  s_slab[10][CCL][33];

    const int cta = blockIdx.x, b = cta >> 2, sl = cta & 3, s0 = sl * 49;
    const int tid = threadIdx.x, w = tid >> 5, lane = tid & 31;
    int j = lane / 10; if (j > 2) j = 2;
    const bool lok = (lane < 30);
    const int c = lok ? (lane - j * 10) : 9;

    // ---- prologue: stats + coords ----
    if (tid < 160) {
        const int cc = tid >> 4, d = tid & 15;
        float nmsv, sivv, cstv = 0.f;
        if (IT == 1) {
            const float* st = g_stats + (b * CCL + cc) * 34;
            nmsv = st[d]; sivv = st[16 + d];
            if (d == 0) cstv = st[32];
        } else {
            float rsum0 = 0.f, sva = 0.f, sv2a = 0.f;
            #pragma unroll
            for (int q = 0; q < 4; q++) {
                const float* p = g_partial + ((b * 4 + q) * CCL + cc) * 34;
                rsum0 += p[0]; sva += p[1 + d]; sv2a += p[17 + d];
            }
            float mean = sva / rsum0;
            float var  = fmaxf(sv2a / rsum0 - mean * mean, 0.f);
            float lg   = __logf(sqrtf(var) + EPSf);
            float cost = (beta_v[cc] + lg) * rsum0, lgs = lg;
            #pragma unroll
            for (int off = 8; off; off >>= 1) {
                cost += __shfl_xor_sync(0xffffffffu, cost, off, 16);
                lgs  += __shfl_xor_sync(0xffffffffu, lgs,  off, 16);
            }
            float oact = 1.f / (1.f + __expf(-2.0f * (beta_a[cc] - cost)));  // invT = 2
            sivv = sqrtf(L2E / (2.f * var + EPSf));
            nmsv = -mean * sivv;
            if (d == 0) cstv = (__logf(oact + EPSf) - lgs) * L2E;
        }
        s_stat[cc * 68 + (d >> 1) * 4 + (d & 1)]     = nmsv;
        s_stat[cc * 68 + (d >> 1) * 4 + 2 + (d & 1)] = sivv;
        if (d == 0) s_cst[cc] = cstv;
    } else if (tid < 209) {
        const int x = tid - 160, s = s0 + x;
        const int h = s / 14, wx = s - h * 14;
        s_coord[x] = make_float2((h + 0.5f) * (1.0f/14.0f), (wx + 0.5f) * (1.0f/14.0f));
    }

    // ---- prologue: stage tiles 0,1 + tail buffer ----
    const float2* pose2 = reinterpret_cast<const float2*>(pose);
    const size_t rowb = (size_t)(b * SSQ + s0) * II;   // global 16-float-row base
    if (tid < 256) {
        const int r = tid >> 3, g = tid & 7, gg = g ^ (r & 7);
        #pragma unroll
        for (int s = 0; s < 2; s++) {
            float2 v = pose2[(rowb + (size_t)s * II + r) * 8 + g];
            s_tile[s * 256 + r * 8 + gg] = make_float4(v.x, v.x, v.y, v.y);
        }
    } else if (tid < 288) {
        const int r = tid - 256;
        s_actr[0][r] = act[rowb + r];
        s_actr[1][r] = act[rowb + II + r];
    }
    for (int x = tid; x < 784; x += 320) {
        const int r = x >> 3, g = x & 7, gg = g ^ (r & 7);
        float2 v = pose2[(rowb + (size_t)(r >> 1) * II + 30 + (r & 1)) * 8 + g];
        s_tailt[r * 8 + gg] = make_float4(v.x, v.x, v.y, v.y);
    }
    for (int x = tid; x < 98; x += 320)
        s_tact[x] = act[rowb + (size_t)(x >> 1) * II + 30 + (x & 1)];
    __syncthreads();

    // ---- per-lane constants ----
    const int i_main = w + 10 * j;       // lanes 30,31: clone (a gated to 0)
    u64 W2[4][2];
    {
        const float* wr = wt + (i_main * CCL + c) * 16;
        #pragma unroll
        for (int q = 0; q < 4; q++) {
            W2[q][0] = pack2(wr[q*4+0], wr[q*4+1]);
            W2[q][1] = pack2(wr[q*4+2], wr[q*4+3]);
        }
    }
    const float cstc = s_cst[c];
    const unsigned stat_base = (unsigned)__cvta_generic_to_shared(s_stat) + (unsigned)(c * 272);
    const unsigned tile_base = (unsigned)__cvta_generic_to_shared(s_tile);
    const unsigned tail_base = (unsigned)__cvta_generic_to_shared(s_tailt);

    int gidx[9];
    #pragma unroll
    for (int k = 1; k <= 9; k++) {
        int cc = c + k; if (cc >= 10) cc -= 10;
        gidx[k - 1] = j * 10 + cc;
    }

    Acc acc;
    #pragma unroll
    for (int jj = 0; jj < 8; jj++) { acc.sv[jj] = 0ULL; acc.sv2[jj] = 0ULL; }
    acc.rsum = 0.f;

    const unsigned rowoff = (unsigned)(i_main * 128);
    const int rk = i_main & 7;

    // ---- main loop: 49 steps, one s per step; barrier only rate-matches tiles ----
    for (int t = 0; t < 49; t++) {
        float2 pfv; float pav;
        const bool dopf = (t <= 46);
        if (dopf) {
            if (tid < 256) {
                const int r = tid >> 3, g = tid & 7;
                pfv = pose2[(rowb + (size_t)(t + 2) * II + r) * 8 + g];
            } else if (tid < 288) {
                pav = act[rowb + (size_t)(t + 2) * II + (tid - 256)];
            }
        }

        const unsigned base = tile_base + (unsigned)((t & 3) << 12) + rowoff;
        const float a = lok ? s_actr[t & 3][i_main] : 0.f;
        process_unit(base, rk, s_coord[t], a, W2, stat_base, cstc, gidx, acc);

        if (dopf) {
            if (tid < 256) {
                const int r = tid >> 3, g = tid & 7, gg = g ^ (r & 7);
                s_tile[((t + 2) & 3) * 256 + r * 8 + gg] = make_float4(pfv.x, pfv.x, pfv.y, pfv.y);
            } else if (tid < 288) {
                s_actr[(t + 2) & 3][tid - 256] = pav;
            }
        }
        __syncthreads();
    }

    // ---- tail: i = 30,31 (j=0 -> 30, j=1 -> 31); barrier-free ----
    {
        const bool tok = (j < 2);
        const int it = 30 + (tok ? j : 0);
        {
            const float* wr = wt + (it * CCL + c) * 16;
            #pragma unroll
            for (int q = 0; q < 4; q++) {
                W2[q][0] = pack2(wr[q*4+0], wr[q*4+1]);
                W2[q][1] = pack2(wr[q*4+2], wr[q*4+3]);
            }
        }
        #pragma unroll
        for (int tau = 0; tau < 5; tau++) {
            const int st = w + 10 * tau;
            const bool v = tok && (st < 49);
            const int stc = v ? st : 48;
            const int r = 2 * stc + (j & 1);
            const float a = v ? s_tact[r] : 0.f;
            process_unit(tail_base + (unsigned)(r * 128), r & 7,
                         s_coord[stc], a, W2, stat_base, cstc, gidx, acc);
        }
    }

    // ---- epilogue: reduce j-groups (lanes c, c+10, c+20 -> lane c) ----
    acc.rsum += __shfl_sync(0xffffffffu, acc.rsum, lane + 10)
              + __shfl_sync(0xffffffffu, acc.rsum, lane + 20);
    #pragma unroll
    for (int jj = 0; jj < 8; jj++) {
        acc.sv[jj]  = add2(acc.sv[jj],  add2(__shfl_sync(0xffffffffu, acc.sv[jj],  lane + 10),
                                             __shfl_sync(0xffffffffu, acc.sv[jj],  lane + 20)));
        acc.sv2[jj] = add2(acc.sv2[jj], add2(__shfl_sync(0xffffffffu, acc.sv2[jj], lane + 10),
                                             __shfl_sync(0xffffffffu, acc.sv2[jj], lane + 20)));
    }
    if (lane < 10) {
        float* o = &s_slab[w][lane][0];
        o[0] = acc.rsum;
        #pragma unroll
        for (int jj = 0; jj < 8; jj++) {
            float lo, hi;
            unpack2(acc.sv[jj],  lo, hi); o[1  + 2*jj] = lo; o[2  + 2*jj] = hi;
            unpack2(acc.sv2[jj], lo, hi); o[17 + 2*jj] = lo; o[18 + 2*jj] = hi;
        }
    }
    __syncthreads();

    // cross-warp (10 warps) sum -> g_partial (grid-strided)
    for (int t = tid; t < CCL * 33; t += 320) {
        const int cc = t / 33, f = t - cc * 33;
        float s = 0.f;
        #pragma unroll
        for (int ww = 0; ww < 10; ww++) s += s_slab[ww][cc][f];
        g_partial[(cta * CCL + cc) * 34 + f] = s;
    }
}

// ---------------- final output ----------------
__global__ __launch_bounds__(160)
void finalize_out(const float* __restrict__ beta_v,
                  const float* __restrict__ beta_a,
                  float* __restrict__ out)
{
    const int b = blockIdx.x;
    const int c = threadIdx.x >> 4;
    const int d = threadIdx.x & 15;

    float rsum = 0.f, sv = 0.f, sv2 = 0.f;
    #pragma unroll
    for (int q = 0; q < 4; q++) {
        const float* p = g_partial + ((b * 4 + q) * CCL + c) * 34;
        rsum += p[0]; sv += p[1 + d]; sv2 += p[17 + d];
    }
    float mean = sv / rsum;
    float var  = fmaxf(sv2 / rsum - mean * mean, 0.f);
    float lg   = __logf(sqrtf(var) + EPSf);
    float cost = (beta_v[c] + lg) * rsum;
    #pragma unroll
    for (int off = 8; off; off >>= 1)
        cost += __shfl_xor_sync(0xffffffffu, cost, off, 16);

    float oact = 1.f / (1.f + __expf(-3.0f * (beta_a[c] - cost)));   // invT = 3

    out[(b * CCL + c) * 16 + d] = mean;
    if (d == 0) out[BB * CCL * 16 + b * CCL + c] = oact;
}

extern "C" void kernel_launch(void* const* d_in, const int* in_sizes, int n_in,
                              void* d_out, int out_size)
{
    const float* pose = (const float*)d_in[0];
    const float* act  = (const float*)d_in[1];
    const float* w    = (const float*)d_in[2];
    const float* bv   = (const float*)d_in[3];
    const float* ba   = (const float*)d_in[4];
    float* out = (float*)d_out;

    pass0_kernel <<<128, 320>>>(pose, act);
    stats0_kernel<<<64, 320>>>(w, bv, ba);
    accum_kernel<1><<<256, 320>>>(pose, act, w, bv, ba);
    accum_kernel<2><<<256, 320>>>(pose, act, w, bv, ba);
    finalize_out <<<64, 160>>>(bv, ba, out);
}

// round 14
// speedup vs baseline: 2.1618x; 1.1980x over previous
#include <cuda_runtime.h>

// EM-routing capsule layer. B=64, S=14, I=32 -> N=6272/batch, C=10, D=16, 3 iters.
// Pass 0 linearized; passes 1-2 stream pose once each, 2 CTAs/SM.
// R14 = R9 (skewed single-bank pipeline, warp=class) with the register prefetch
// replaced by cp.async (LDGSTS) into a ring-4 tile buffer at pipeline depth 2:
// region k issues tile k+3, wait_group(2) before the barrier guarantees k+1.
// Removes the LDG->STS scoreboard exposure at region end.

#define BB   64
#define SSQ  196
#define II   32
#define CCL  10
#define EPSf 1e-9f
#define L2E  1.4426950408889634f

typedef unsigned long long u64;

__device__ float g0[128 * 10 * 69 * 32];        // pass0 per-(cta,warp) slabs
__device__ float g_partial[256 * CCL * 34];     // per (b*4+sl, c): [0]=rsum [1..16]=sv [17..32]=sv2
__device__ float g_stats[BB * CCL * 34];        // per (b,c): [0..15]=nms [16..31]=siv [32]=cst (log2)

__device__ __forceinline__ u64 pack2(float lo, float hi) {
    u64 r; asm("mov.b64 %0,{%1,%2};" : "=l"(r) : "f"(lo), "f"(hi)); return r;
}
__device__ __forceinline__ void unpack2(u64 v, float& lo, float& hi) {
    asm("mov.b64 {%0,%1},%2;" : "=f"(lo), "=f"(hi) : "l"(v));
}
__device__ __forceinline__ u64 fma2(u64 a, u64 b, u64 c) {
    u64 d; asm("fma.rn.f32x2 %0,%1,%2,%3;" : "=l"(d) : "l"(a), "l"(b), "l"(c)); return d;
}
__device__ __forceinline__ u64 add2(u64 a, u64 b) {
    u64 d; asm("add.rn.f32x2 %0,%1,%2;" : "=l"(d) : "l"(a), "l"(b)); return d;
}
__device__ __forceinline__ u64 mul2(u64 a, u64 b) {
    u64 d; asm("mul.rn.f32x2 %0,%1,%2;" : "=l"(d) : "l"(a), "l"(b)); return d;
}
__device__ __forceinline__ float ex2f(float x) {
    float y; asm("ex2.approx.f32 %0,%1;" : "=f"(y) : "f"(x)); return y;
}
__device__ __forceinline__ void cp16(unsigned dst, const void* src) {
    asm volatile("cp.async.cg.shared.global [%0], [%1], 16;" :: "r"(dst), "l"(src));
}
__device__ __forceinline__ void cp4(unsigned dst, const void* src) {
    asm volatile("cp.async.ca.shared.global [%0], [%1], 4;" :: "r"(dst), "l"(src));
}
#define CP_COMMIT() asm volatile("cp.async.commit_group;" ::: "memory")
#define CP_WAIT2()  asm volatile("cp.async.wait_group 2;"  ::: "memory")

// ---------------- pass 0: linear/quadratic reduction over pose ----------------
__global__ __launch_bounds__(320, 1)
void pass0_kernel(const float* __restrict__ pose, const float* __restrict__ act)
{
    const int cta = blockIdx.x, b = cta >> 1, half = cta & 1;
    const int wpid = threadIdx.x >> 5, i = threadIdx.x & 31;

    float aP[16], G[40], X1[4], X2[4];
    float ra = 0.f, rc1 = 0.f, rc2 = 0.f, rq1 = 0.f, rq2 = 0.f;
    #pragma unroll
    for (int f = 0; f < 16; f++) aP[f] = 0.f;
    #pragma unroll
    for (int f = 0; f < 40; f++) G[f] = 0.f;
    #pragma unroll
    for (int f = 0; f < 4; f++) { X1[f] = 0.f; X2[f] = 0.f; }

    for (int sl = wpid; sl < 98; sl += 10) {
        const int s  = half * 98 + sl;
        const int h  = s / 14;
        const int wx = s - h * 14;
        const float cr = (h  + 0.5f) * (1.0f / 14.0f);
        const float cw = (wx + 0.5f) * (1.0f / 14.0f);

        const size_t nidx = ((size_t)(b * SSQ + s) * II + i);
        const float4* pv = reinterpret_cast<const float4*>(pose + nidx * 16);
        float p16[16];
        #pragma unroll
        for (int q4 = 0; q4 < 4; q4++) {
            float4 t = pv[q4];
            p16[q4*4+0] = t.x; p16[q4*4+1] = t.y; p16[q4*4+2] = t.z; p16[q4*4+3] = t.w;
        }
        const float a = act[nidx];

        #pragma unroll
        for (int p = 0; p < 4; p++) {
            float t0 = a * p16[p*4+0], t1 = a * p16[p*4+1];
            float t2 = a * p16[p*4+2], t3 = a * p16[p*4+3];
            aP[p*4+0] += t0; aP[p*4+1] += t1; aP[p*4+2] += t2; aP[p*4+3] += t3;
            float* Gp = G + p * 10;
            Gp[0] = fmaf(t0, p16[p*4+0], Gp[0]);
            Gp[1] = fmaf(t0, p16[p*4+1], Gp[1]);
            Gp[2] = fmaf(t0, p16[p*4+2], Gp[2]);
            Gp[3] = fmaf(t0, p16[p*4+3], Gp[3]);
            Gp[4] = fmaf(t1, p16[p*4+1], Gp[4]);
            Gp[5] = fmaf(t1, p16[p*4+2], Gp[5]);
            Gp[6] = fmaf(t1, p16[p*4+3], Gp[6]);
            Gp[7] = fmaf(t2, p16[p*4+2], Gp[7]);
            Gp[8] = fmaf(t2, p16[p*4+3], Gp[8]);
            Gp[9] = fmaf(t3, p16[p*4+3], Gp[9]);
        }
        ra += a;
        const float acr = a * cr, acw = a * cw;
        rc1 += acr; rc2 += acw;
        rq1 = fmaf(acr, cr, rq1); rq2 = fmaf(acw, cw, rq2);
        #pragma unroll
        for (int q = 0; q < 4; q++) {
            X1[q] = fmaf(acr, p16[q], X1[q]);
            X2[q] = fmaf(acw, p16[q], X2[q]);
        }
    }

    float* o = g0 + (size_t)(cta * 10 + wpid) * 69 * 32 + i;
    #pragma unroll
    for (int f = 0; f < 16; f++) o[f * 32] = aP[f];
    #pragma unroll
    for (int f = 0; f < 40; f++) o[(16 + f) * 32] = G[f];
    o[56 * 32] = ra;
    o[57 * 32] = rc1; o[58 * 32] = rc2;
    o[59 * 32] = rq1; o[60 * 32] = rq2;
    #pragma unroll
    for (int f = 0; f < 4; f++) { o[(61 + f) * 32] = X1[f]; o[(65 + f) * 32] = X2[f]; }
}

// ---------------- pass 0 stats ----------------
__global__ __launch_bounds__(320, 1)
void stats0_kernel(const float* __restrict__ wt,
                   const float* __restrict__ beta_v,
                   const float* __restrict__ beta_a)
{
    __shared__ float sm[32][72];
    const int b = blockIdx.x, tid = threadIdx.x;

    for (int t = tid; t < 32 * 69; t += 320) {
        const int i = t / 69, f = t - i * 69;
        float s = 0.f;
        #pragma unroll
        for (int k = 0; k < 20; k++) {
            const int cta = b * 2 + (k >= 10 ? 1 : 0);
            const int ww  = k - (k >= 10 ? 10 : 0);
            s += g0[(size_t)(cta * 10 + ww) * 69 * 32 + f * 32 + i];
        }
        sm[i][f] = s;
    }
    __syncthreads();

    if (tid < 160) {
        const int c = tid >> 4, d = tid & 15, p = d >> 2, r = d & 3;
        float RA = 0.f, RC = 0.f, RQ = 0.f, Sv = 0.f, Sv2 = 0.f, Cr = 0.f;
        for (int i = 0; i < 32; i++) {
            const float* g = sm[i];
            const float* wr = wt + (i * CCL + c) * 16;
            const float W0 = wr[0*4+r], W1 = wr[1*4+r], W2 = wr[2*4+r], W3 = wr[3*4+r];
            const float* ap = g + p * 4;
            Sv += ap[0]*W0 + ap[1]*W1 + ap[2]*W2 + ap[3]*W3;
            const float* Gp = g + 16 + p * 10;
            Sv2 += W0*W0*Gp[0] + W1*W1*Gp[4] + W2*W2*Gp[7] + W3*W3*Gp[9]
                 + 2.f*(W0*W1*Gp[1] + W0*W2*Gp[2] + W0*W3*Gp[3]
                      + W1*W2*Gp[5] + W1*W3*Gp[6] + W2*W3*Gp[8]);
            RA += g[56];
            if (d == 0) { RC += g[57]; RQ += g[59]; Cr += W0*g[61]+W1*g[62]+W2*g[63]+W3*g[64]; }
            else if (d == 1) { RC += g[58]; RQ += g[60]; Cr += W0*g[65]+W1*g[66]+W2*g[67]+W3*g[68]; }
        }
        float coordm = (d == 0 || d == 1) ? RC : 0.f;
        float coordv = (d == 0 || d == 1) ? (2.f * Cr + RQ) : 0.f;
        float mean = (Sv + coordm) / RA;
        float var  = fmaxf((Sv2 + coordv) / RA - mean * mean, 0.f);
        float lg   = __logf(sqrtf(var) + EPSf);
        float rr_sum = RA * 0.1f;
        float cost = (beta_v[c] + lg) * rr_sum, lgs = lg;
        #pragma unroll
        for (int off = 8; off; off >>= 1) {
            cost += __shfl_xor_sync(0xffffffffu, cost, off, 16);
            lgs  += __shfl_xor_sync(0xffffffffu, lgs,  off, 16);
        }
        float oact = 1.f / (1.f + __expf(-(beta_a[c] - cost)));   // invT = 1
        float siv  = sqrtf(L2E / (2.f * var + EPSf));
        float* st = g_stats + (b * CCL + c) * 34;
        st[d]      = -mean * siv;
        st[16 + d] = siv;
        if (d == 0) st[32] = (__logf(oact + EPSf) - lgs) * L2E;
    }
}

// ---------------- routing passes 1 and 2 ----------------

// votes + zz for spatial index K (ring-4 tile); fills V2/ZC/AC; stores zz
#define COMPUTE_BODY(K, V2, ZC, AC) {                                          \
    const float2 _cc2 = s_coord[(K)];                                          \
    V2[0] = pack2(_cc2.x, _cc2.y);                                             \
    _Pragma("unroll")                                                          \
    for (int _j = 1; _j < 8; _j++) V2[_j] = 0ULL;                              \
    _Pragma("unroll")                                                          \
    for (int _p = 0; _p < 4; _p++) {                                           \
        float4 _tp = s_tile[(K) & 3][sxp[_p]];                                 \
        u64 _pp;                                                               \
        _pp = pack2(_tp.x, _tp.x);                                             \
        V2[_p*2+0] = fma2(_pp, W2[0][0], V2[_p*2+0]);                          \
        V2[_p*2+1] = fma2(_pp, W2[0][1], V2[_p*2+1]);                          \
        _pp = pack2(_tp.y, _tp.y);                                             \
        V2[_p*2+0] = fma2(_pp, W2[1][0], V2[_p*2+0]);                          \
        V2[_p*2+1] = fma2(_pp, W2[1][1], V2[_p*2+1]);                          \
        _pp = pack2(_tp.z, _tp.z);                                             \
        V2[_p*2+0] = fma2(_pp, W2[2][0], V2[_p*2+0]);                          \
        V2[_p*2+1] = fma2(_pp, W2[2][1], V2[_p*2+1]);                          \
        _pp = pack2(_tp.w, _tp.w);                                             \
        V2[_p*2+0] = fma2(_pp, W2[3][0], V2[_p*2+0]);                          \
        V2[_p*2+1] = fma2(_pp, W2[3][1], V2[_p*2+1]);                          \
    }                                                                          \
    AC = s_actr[(K) & 3][lane];                                                \
    u64 _az0 = 0ULL, _az1 = 0ULL;                                              \
    _Pragma("unroll")                                                          \
    for (int _j = 0; _j < 8; _j++) {                                           \
        u64 _nm, _sviv;                                                        \
        asm volatile("ld.shared.v2.b64 {%0,%1},[%2];"                          \
                     : "=l"(_nm), "=l"(_sviv) : "r"(stat_base + 16u * _j));    \
        u64 _t = fma2(V2[_j], _sviv, _nm);                                     \
        if (_j & 1) _az1 = fma2(_t, _t, _az1);                                 \
        else        _az0 = fma2(_t, _t, _az0);                                 \
    }                                                                          \
    { float _l0,_h0,_l1,_h1; unpack2(_az0,_l0,_h0); unpack2(_az1,_l1,_h1);     \
      ZC = cstc - ((_l0 + _l1) + (_h0 + _h1)); }                               \
    s_zz[(K) & 1][czz + lane] = ZC;                                            \
}

// softmax + accumulate for spatial index K (consumes V2/ZC/AC)
#define FINISH(K, V2, ZC, AC) {                                                \
    const float* _zr = &s_zz[(K) & 1][lane];                                   \
    float _Z0 = 0.f, _Z1 = 0.f;                                                \
    _Pragma("unroll")                                                          \
    for (int _j = 0; _j < 10; _j++) {                                          \
        float _e = ex2f(_zr[_j * 32] - ZC);                                    \
        if (_j & 1) _Z1 += _e; else _Z0 += _e;                                 \
    }                                                                          \
    const float _rrp = __fdividef(AC, _Z0 + _Z1);                              \
    rsum += _rrp;                                                              \
    const u64 _rr2 = pack2(_rrp, _rrp);                                        \
    _Pragma("unroll")                                                          \
    for (int _j = 0; _j < 8; _j++) {                                           \
        const u64 _rv = mul2(_rr2, V2[_j]);                                    \
        sv[_j]  = add2(sv[_j], _rv);                                           \
        sv2[_j] = fma2(_rv, V2[_j], sv2[_j]);                                  \
    }                                                                          \
}

template<int IT>
__global__ __launch_bounds__(320, 2)
void accum_kernel(const float* __restrict__ pose,
                  const float* __restrict__ act,
                  const float* __restrict__ wt,
                  const float* __restrict__ beta_v,
                  const float* __restrict__ beta_a)
{
    __shared__ float4 s_tile[4][128];                  // ring-4 tiles (2KB each)
    __shared__ float  s_actr[4][32];
    __shared__ float  s_zz[2][320];                    // [buf][c*32 + i], conflict-free
    __shared__ __align__(16) float s_stat[CCL][8][4];  // per pair j: nms0,nms1,siv0,siv1
    __shared__ float  s_cst[CCL];
    __shared__ float2 s_coord[49];

    const int cta = blockIdx.x, b = cta >> 2, sl = cta & 3;
    const int tid = threadIdx.x, c = tid >> 5, lane = tid & 31;
    const int s0 = sl * 49;
    const int czz = c * 32;

    // ---- stats into smem ----
    if (tid < 160) {
        const int cc = tid >> 4, d = tid & 15;
        float nmsv, sivv, cstv = 0.f;
        if (IT == 1) {
            const float* st = g_stats + (b * CCL + cc) * 34;
            nmsv = st[d]; sivv = st[16 + d];
            if (d == 0) cstv = st[32];
        } else {
            float rsum0 = 0.f, sva = 0.f, sv2a = 0.f;
            #pragma unroll
            for (int q = 0; q < 4; q++) {
                const float* p = g_partial + ((b * 4 + q) * CCL + cc) * 34;
                rsum0 += p[0]; sva += p[1 + d]; sv2a += p[17 + d];
            }
            float mean = sva / rsum0;
            float var  = fmaxf(sv2a / rsum0 - mean * mean, 0.f);
            float lg   = __logf(sqrtf(var) + EPSf);
            float cost = (beta_v[cc] + lg) * rsum0, lgs = lg;
            #pragma unroll
            for (int off = 8; off; off >>= 1) {
                cost += __shfl_xor_sync(0xffffffffu, cost, off, 16);
                lgs  += __shfl_xor_sync(0xffffffffu, lgs,  off, 16);
            }
            float oact = 1.f / (1.f + __expf(-2.0f * (beta_a[cc] - cost)));  // invT = 2
            sivv = sqrtf(L2E / (2.f * var + EPSf));
            nmsv = -mean * sivv;
            if (d == 0) cstv = (__logf(oact + EPSf) - lgs) * L2E;
        }
        s_stat[cc][d >> 1][d & 1]       = nmsv;
        s_stat[cc][d >> 1][2 + (d & 1)] = sivv;
        if (d == 0) s_cst[cc] = cstv;
    } else if (tid >= 256 && tid < 305) {
        const int s = s0 + (tid - 256);
        const int h = s / 14, wx = s - h * 14;
        s_coord[tid - 256] = make_float2((h + 0.5f) * (1.0f/14.0f), (wx + 0.5f) * (1.0f/14.0f));
    }

    // ---- cp.async staging: tiles 0,1,2 as groups 0,1,2 ----
    const float4* pose4 = reinterpret_cast<const float4*>(pose);
    const size_t nb0 = ((size_t)(b * SSQ) + s0) * II;
    const float4* psrc = pose4 + nb0 * 4;        // tile k at psrc + k*128
    const float*  asrc = act + nb0;              // act  k at asrc + k*32

    const unsigned tile_smem = (unsigned)__cvta_generic_to_shared(s_tile);
    const unsigned act_smem  = (unsigned)__cvta_generic_to_shared(s_actr);
    unsigned my_dst = 0;
    if (tid < 128) {
        const int sx = tid ^ ((tid >> 3) & 7);
        my_dst = tile_smem + (unsigned)(sx * 16);
    } else if (tid < 160) {
        my_dst = act_smem + (unsigned)((tid - 128) * 4);
    }

    #pragma unroll
    for (int s = 0; s < 3; s++) {
        if (tid < 128)      cp16(my_dst + (unsigned)(s * 2048), psrc + s * 128 + tid);
        else if (tid < 160) cp4(my_dst + (unsigned)(s * 128), asrc + s * II + (tid - 128));
        CP_COMMIT();
    }
    CP_WAIT2();          // tile 0 complete
    __syncthreads();     // stats + tile 0 visible

    // ---- per-warp constants ----
    u64 W2[4][2];
    {
        const float* wr = wt + (lane * CCL + c) * 16;
        #pragma unroll
        for (int q = 0; q < 4; q++) {
            W2[q][0] = pack2(wr[q*4+0], wr[q*4+1]);
            W2[q][1] = pack2(wr[q*4+2], wr[q*4+3]);
        }
    }
    const float cstc = s_cst[c];
    const unsigned stat_base = (unsigned)__cvta_generic_to_shared(&s_stat[c][0][0]);

    int sxp[4];
    #pragma unroll
    for (int p = 0; p < 4; p++) {
        const int idx = lane * 4 + p;
        sxp[p] = idx ^ ((idx >> 3) & 7);
    }

    u64 sv[8], sv2[8];
    #pragma unroll
    for (int j = 0; j < 8; j++) { sv[j] = 0ULL; sv2[j] = 0ULL; }
    float rsum = 0.f;

    u64 vA[8]; float zcA, aA;

    // region 0: issue tile 3, compute s=0
    {
        if (tid < 128)      cp16(my_dst + (unsigned)((3 & 3) * 2048), psrc + 3 * 128 + tid);
        else if (tid < 160) cp4(my_dst + (unsigned)((3 & 3) * 128), asrc + 3 * II + (tid - 128));
        CP_COMMIT();
        COMPUTE_BODY(0, vA, zcA, aA);
        CP_WAIT2();      // tile 1 complete
    }
    __syncthreads();

    // regions 1..48: issue(k+3) | finish(k-1) | compute(k) | wait(k+1 ready)
    for (int k = 1; k < 49; k++) {
        const int kk = k + 3;
        if (kk < 49) {
            if (tid < 128)      cp16(my_dst + (unsigned)((kk & 3) * 2048), psrc + kk * 128 + tid);
            else if (tid < 160) cp4(my_dst + (unsigned)((kk & 3) * 128), asrc + kk * II + (tid - 128));
        }
        CP_COMMIT();

        FINISH(k - 1, vA, zcA, aA);
        COMPUTE_BODY(k, vA, zcA, aA);

        CP_WAIT2();
        __syncthreads();
    }
    FINISH(48, vA, zcA, aA);

    // reduce over the 32 lanes (capsule i)
    #pragma unroll
    for (int off = 16; off; off >>= 1) {
        rsum += __shfl_xor_sync(0xffffffffu, rsum, off);
        #pragma unroll
        for (int j = 0; j < 8; j++) {
            sv[j]  = add2(sv[j],  __shfl_xor_sync(0xffffffffu, sv[j],  off));
            sv2[j] = add2(sv2[j], __shfl_xor_sync(0xffffffffu, sv2[j], off));
        }
    }
    if (lane == 0) {
        float* o = g_partial + (cta * CCL + c) * 34;
        o[0] = rsum;
        #pragma unroll
        for (int j = 0; j < 8; j++) {
            float lo, hi;
            unpack2(sv[j],  lo, hi); o[1  + 2*j] = lo; o[2  + 2*j] = hi;
            unpack2(sv2[j], lo, hi); o[17 + 2*j] = lo; o[18 + 2*j] = hi;
        }
    }
}

// ---------------- final output ----------------
__global__ __launch_bounds__(160)
void finalize_out(const float* __restrict__ beta_v,
                  const float* __restrict__ beta_a,
                  float* __restrict__ out)
{
    const int b = blockIdx.x;
    const int c = threadIdx.x >> 4;
    const int d = threadIdx.x & 15;

    float rsum = 0.f, sv = 0.f, sv2 = 0.f;
    #pragma unroll
    for (int q = 0; q < 4; q++) {
        const float* p = g_partial + ((b * 4 + q) * CCL + c) * 34;
        rsum += p[0]; sv += p[1 + d]; sv2 += p[17 + d];
    }
    float mean = sv / rsum;
    float var  = fmaxf(sv2 / rsum - mean * mean, 0.f);
    float lg   = __logf(sqrtf(var) + EPSf);
    float cost = (beta_v[c] + lg) * rsum;
    #pragma unroll
    for (int off = 8; off; off >>= 1)
        cost += __shfl_xor_sync(0xffffffffu, cost, off, 16);

    float oact = 1.f / (1.f + __expf(-3.0f * (beta_a[c] - cost)));   // invT = 3

    out[(b * CCL + c) * 16 + d] = mean;
    if (d == 0) out[BB * CCL * 16 + b * CCL + c] = oact;
}

extern "C" void kernel_launch(void* const* d_in, const int* in_sizes, int n_in,
                              void* d_out, int out_size)
{
    const float* pose = (const float*)d_in[0];
    const float* act  = (const float*)d_in[1];
    const float* w    = (const float*)d_in[2];
    const float* bv   = (const float*)d_in[3];
    const float* ba   = (const float*)d_in[4];
    float* out = (float*)d_out;

    pass0_kernel <<<128, 320>>>(pose, act);
    stats0_kernel<<<64, 320>>>(w, bv, ba);
    accum_kernel<1><<<256, 320>>>(pose, act, w, bv, ba);
    accum_kernel<2><<<256, 320>>>(pose, act, w, bv, ba);
    finalize_out <<<64, 160>>>(bv, ba, out);
}